// round 5
// baseline (speedup 1.0000x reference)
#include <cuda_runtime.h>

#define BB 4
#define NN 512
#define DD 256
#define EE 64
#define HH 4

// ---------------- scratch (no allocation allowed) ----------------
__device__ float g_q[HH*BB*NN*EE];          // [h][b][n][e]   2 MB
__device__ float g_k[HH*BB*NN*EE];          // 2 MB
__device__ float g_v[HH*BB*NN*EE];          // 2 MB
__device__ float g_logits[HH*BB*NN*NN];     // [h][b][n][m]  16 MB (raw logits)

// ---------------- 1) fused QKV projection ----------------
// per block: 64 rows (n) x 64 cols (e) of one (s,h); K loop over D=256.
__global__ __launch_bounds__(256) void proj_kernel(
    const float* __restrict__ x,
    const float* __restrict__ Wq, const float* __restrict__ bq,
    const float* __restrict__ Wk, const float* __restrict__ bk,
    const float* __restrict__ Wv, const float* __restrict__ bv)
{
    const int ct = blockIdx.x;            // 0..11 -> (s,h)
    const int rt = blockIdx.y;            // 0..7 row tile
    const int b  = blockIdx.z;
    const int s = ct >> 2, h = ct & 3;

    const float* W   = (s == 0 ? Wq : (s == 1 ? Wk : Wv)) + h * DD * EE;
    const float* bia = (s == 0 ? bq : (s == 1 ? bk : bv)) + h * EE;
    float* out = (s == 0 ? g_q : (s == 1 ? g_k : g_v)) + (size_t)(h * BB + b) * NN * EE;
    const float* X = x + (size_t)(b * NN + rt * 64) * DD;

    __shared__ float As[32][64];   // [kk][row]  (transposed)
    __shared__ float Bs[32][64];   // [kk][col]

    const int tid = threadIdx.x;
    const int tx = tid & 15, ty = tid >> 4;

    float acc[4][4] = {};

    for (int kc = 0; kc < DD; kc += 32) {
        #pragma unroll
        for (int t = 0; t < 2; t++) {
            int lin = tid + t * 256;                  // 0..511 float4 units
            int r = lin >> 3, c = (lin & 7) * 4;      // A: row r, k-offset c
            float4 va = *(const float4*)&X[r * DD + kc + c];
            As[c + 0][r] = va.x; As[c + 1][r] = va.y;
            As[c + 2][r] = va.z; As[c + 3][r] = va.w;
            int kk = lin >> 4, cc = (lin & 15) * 4;   // B: k row kk, col cc
            float4 vb = *(const float4*)&W[(kc + kk) * EE + cc];
            *(float4*)&Bs[kk][cc] = vb;
        }
        __syncthreads();
        #pragma unroll
        for (int kk = 0; kk < 32; kk++) {
            float4 a  = *(const float4*)&As[kk][ty * 4];
            float4 bb = *(const float4*)&Bs[kk][tx * 4];
            float av[4] = {a.x, a.y, a.z, a.w};
            float bw[4] = {bb.x, bb.y, bb.z, bb.w};
            #pragma unroll
            for (int i = 0; i < 4; i++)
                #pragma unroll
                for (int j = 0; j < 4; j++)
                    acc[i][j] = fmaf(av[i], bw[j], acc[i][j]);
        }
        __syncthreads();
    }

    #pragma unroll
    for (int i = 0; i < 4; i++) {
        float4 o;
        o.x = acc[i][0] + bia[tx * 4 + 0];
        o.y = acc[i][1] + bia[tx * 4 + 1];
        o.z = acc[i][2] + bia[tx * 4 + 2];
        o.w = acc[i][3] + bia[tx * 4 + 3];
        *(float4*)&out[(size_t)(rt * 64 + ty * 4 + i) * EE + tx * 4] = o;
    }
}

// ---------------- 2) logits per head (templated on attention flavor) ----------------
// HEAD: 0=sdp, 1=cosine, 2=L1, 3=L2
// Row-major tiles with stride 68 (68 mod 32 = 4): LDS.128 of 4 e-values per
// row is conflict-free across the 16 tx lanes (banks 4tx..4tx+3 per phase).
template<int HEAD>
__global__ __launch_bounds__(256) void logits_kernel()
{
    const int jt = blockIdx.x, it = blockIdx.y, b = blockIdx.z;
    const float* Q = g_q + ((size_t)(HEAD * BB + b) * NN + it * 64) * EE;
    const float* K = g_k + ((size_t)(HEAD * BB + b) * NN + jt * 64) * EE;
    float* L = g_logits + ((size_t)(HEAD * BB + b) * NN + it * 64) * NN + jt * 64;

    __shared__ float Qs[64][68];
    __shared__ float Ks[64][68];
    __shared__ float rn[128];      // [0..63]=1/|q_i|, [64..127]=1/|k_j| (cosine only)

    const int tid = threadIdx.x;
    const int tx = tid & 15, ty = tid >> 4;

    #pragma unroll
    for (int t = 0; t < 4; t++) {
        int lin = tid + t * 256;               // 0..1023 float4 units
        int r = lin >> 4, c = (lin & 15) * 4;
        *(float4*)&Qs[r][c] = *(const float4*)&Q[r * EE + c];
        *(float4*)&Ks[r][c] = *(const float4*)&K[r * EE + c];
    }
    __syncthreads();

    if (HEAD == 1) {
        if (tid < 128) {
            int r = tid & 63;
            const float (*S)[68] = (tid < 64) ? Qs : Ks;
            float ss = 0.f;
            #pragma unroll 8
            for (int e = 0; e < EE; e++) { float v = S[r][e]; ss = fmaf(v, v, ss); }
            rn[tid] = rsqrtf(ss);
        }
        __syncthreads();
    }

    // rows i = ty*4+ii, cols j = tx + 16*jj; e unrolled by 4 via float4 LDS
    float acc[4][4] = {};
    #pragma unroll
    for (int e = 0; e < EE; e += 4) {
        float4 q4[4], k4[4];
        #pragma unroll
        for (int ii = 0; ii < 4; ii++) q4[ii] = *(const float4*)&Qs[ty * 4 + ii][e];
        #pragma unroll
        for (int jj = 0; jj < 4; jj++) k4[jj] = *(const float4*)&Ks[tx + 16 * jj][e];
        #pragma unroll
        for (int ii = 0; ii < 4; ii++)
            #pragma unroll
            for (int jj = 0; jj < 4; jj++) {
                if (HEAD <= 1) {
                    acc[ii][jj] = fmaf(q4[ii].x, k4[jj].x, acc[ii][jj]);
                    acc[ii][jj] = fmaf(q4[ii].y, k4[jj].y, acc[ii][jj]);
                    acc[ii][jj] = fmaf(q4[ii].z, k4[jj].z, acc[ii][jj]);
                    acc[ii][jj] = fmaf(q4[ii].w, k4[jj].w, acc[ii][jj]);
                } else if (HEAD == 2) {
                    acc[ii][jj] += fabsf(q4[ii].x - k4[jj].x);
                    acc[ii][jj] += fabsf(q4[ii].y - k4[jj].y);
                    acc[ii][jj] += fabsf(q4[ii].z - k4[jj].z);
                    acc[ii][jj] += fabsf(q4[ii].w - k4[jj].w);
                } else {
                    float d0 = q4[ii].x - k4[jj].x;
                    float d1 = q4[ii].y - k4[jj].y;
                    float d2 = q4[ii].z - k4[jj].z;
                    float d3 = q4[ii].w - k4[jj].w;
                    acc[ii][jj] = fmaf(d0, d0, acc[ii][jj]);
                    acc[ii][jj] = fmaf(d1, d1, acc[ii][jj]);
                    acc[ii][jj] = fmaf(d2, d2, acc[ii][jj]);
                    acc[ii][jj] = fmaf(d3, d3, acc[ii][jj]);
                }
            }
    }

    #pragma unroll
    for (int ii = 0; ii < 4; ii++) {
        #pragma unroll
        for (int jj = 0; jj < 4; jj++) {
            float v = acc[ii][jj];
            if (HEAD == 0)      v *= 0.125f;                       // 1/sqrt(E)
            else if (HEAD == 1) v *= rn[ty * 4 + ii] * rn[64 + tx + 16 * jj];
            else if (HEAD == 2) v = -v;
            else                v = -sqrtf(v);
            L[(size_t)(ty * 4 + ii) * NN + tx + 16 * jj] = v;
        }
    }
}

// ---------------- 3) fused softmax + P @ V + head concat ----------------
// block = (it: 32 tiles of 16 rows, h, b). Stages 16x512 raw logits in smem,
// does row softmax in-smem, then P@V with 1/sum folded into the epilogue.
__global__ __launch_bounds__(256) void av_kernel(float* __restrict__ out)
{
    const int it = blockIdx.x, h = blockIdx.y, b = blockIdx.z;
    const float* P = g_logits + ((size_t)(h * BB + b) * NN + it * 16) * NN;
    const float* V = g_v + (size_t)(h * BB + b) * NN * EE;
    float* O = out + ((size_t)(b * NN + it * 16)) * (HH * EE) + h * EE;

    __shared__ float Ls[16][516];   // stride 516 (16B-aligned rows)
    __shared__ float Vs[32][64];
    __shared__ float invs[16];

    const int tid = threadIdx.x;

    // --- stage raw logits tile (16 rows x 512) ---
    for (int i = tid; i < 16 * 128; i += 256) {      // 2048 float4 loads
        int r = i >> 7, c = (i & 127) * 4;
        *(float4*)&Ls[r][c] = *(const float4*)&P[(size_t)r * NN + c];
    }
    __syncthreads();

    // --- in-smem row softmax (exp stored, 1/sum deferred to epilogue) ---
    {
        const int warp = tid >> 5, lane = tid & 31;
        #pragma unroll
        for (int rr = 0; rr < 2; rr++) {
            const int r = warp * 2 + rr;
            float vals[16];
            float m = -1e30f;
            #pragma unroll
            for (int t = 0; t < 16; t++) { vals[t] = Ls[r][lane + t * 32]; m = fmaxf(m, vals[t]); }
            #pragma unroll
            for (int o = 16; o; o >>= 1) m = fmaxf(m, __shfl_xor_sync(0xffffffffu, m, o));
            float sum = 0.f;
            #pragma unroll
            for (int t = 0; t < 16; t++) {
                vals[t] = __expf(vals[t] - m);
                Ls[r][lane + t * 32] = vals[t];
                sum += vals[t];
            }
            #pragma unroll
            for (int o = 16; o; o >>= 1) sum += __shfl_xor_sync(0xffffffffu, sum, o);
            if (lane == 0) invs[r] = 1.0f / sum;
        }
    }
    __syncthreads();

    // --- P @ V: thread = (row ty, 4 e-cols at tx*4); kk unrolled by 4 ---
    const int tx = tid & 15, ty = tid >> 4;
    float ax = 0.f, ay = 0.f, az = 0.f, aw = 0.f;
    for (int kc = 0; kc < NN; kc += 32) {
        #pragma unroll
        for (int t = 0; t < 2; t++) {
            int lin = tid + t * 256;
            int kk = lin >> 4, c = (lin & 15) * 4;
            *(float4*)&Vs[kk][c] = *(const float4*)&V[(size_t)(kc + kk) * EE + c];
        }
        __syncthreads();
        #pragma unroll
        for (int kk = 0; kk < 32; kk += 4) {
            float4 p = *(const float4*)&Ls[ty][kc + kk];     // broadcast within half-warp
            float4 v0 = *(const float4*)&Vs[kk + 0][tx * 4];
            float4 v1 = *(const float4*)&Vs[kk + 1][tx * 4];
            float4 v2 = *(const float4*)&Vs[kk + 2][tx * 4];
            float4 v3 = *(const float4*)&Vs[kk + 3][tx * 4];
            ax = fmaf(p.x, v0.x, ax); ay = fmaf(p.x, v0.y, ay);
            az = fmaf(p.x, v0.z, az); aw = fmaf(p.x, v0.w, aw);
            ax = fmaf(p.y, v1.x, ax); ay = fmaf(p.y, v1.y, ay);
            az = fmaf(p.y, v1.z, az); aw = fmaf(p.y, v1.w, aw);
            ax = fmaf(p.z, v2.x, ax); ay = fmaf(p.z, v2.y, ay);
            az = fmaf(p.z, v2.z, az); aw = fmaf(p.z, v2.w, aw);
            ax = fmaf(p.w, v3.x, ax); ay = fmaf(p.w, v3.y, ay);
            az = fmaf(p.w, v3.z, az); aw = fmaf(p.w, v3.w, aw);
        }
        __syncthreads();
    }
    const float inv = invs[ty];
    float4 o = { ax * inv, ay * inv, az * inv, aw * inv };
    *(float4*)&O[(size_t)ty * (HH * EE) + tx * 4] = o;
}

// ---------------- launch ----------------
extern "C" void kernel_launch(void* const* d_in, const int* in_sizes, int n_in,
                              void* d_out, int out_size)
{
    (void)in_sizes; (void)n_in; (void)out_size;
    const float* x  = (const float*)d_in[0];
    const float* Wq = (const float*)d_in[1];
    const float* bq = (const float*)d_in[2];
    const float* Wk = (const float*)d_in[3];
    const float* bk = (const float*)d_in[4];
    const float* Wv = (const float*)d_in[5];
    const float* bv = (const float*)d_in[6];
    float* out = (float*)d_out;

    proj_kernel<<<dim3(12, 8, BB), 256>>>(x, Wq, bq, Wk, bk, Wv, bv);
    logits_kernel<0><<<dim3(8, 8, BB), 256>>>();
    logits_kernel<1><<<dim3(8, 8, BB), 256>>>();
    logits_kernel<2><<<dim3(8, 8, BB), 256>>>();
    logits_kernel<3><<<dim3(8, 8, BB), 256>>>();
    av_kernel<<<dim3(32, HH, BB), 256>>>(out);
}

// round 15
// speedup vs baseline: 1.0506x; 1.0506x over previous
#include <cuda_runtime.h>

#define BB 4
#define NN 512
#define DD 256
#define EE 64
#define HH 4

// ---------------- scratch (no allocation allowed) ----------------
__device__ float g_q[HH*BB*NN*EE];          // [h][b][n][e]   2 MB
__device__ float g_k[HH*BB*NN*EE];          // 2 MB
__device__ float g_v[HH*BB*NN*EE];          // 2 MB
__device__ float g_logits[HH*BB*NN*NN];     // [h][b][n][m]  16 MB (raw logits)
__device__ float g_qn[BB*NN];               // head-3 q row sq-norms
__device__ float g_kn[BB*NN];               // head-3 k row sq-norms

// ---------------- 1) fused QKV projection (+ norm epilogues) ----------------
// per block: 64 rows (n) x 64 cols (e) of one (s,h); K loop over D=256.
// Epilogue: head 1 q/k rows are normalized in place (cosine -> plain GEMM);
// head 3 q/k row sq-norms stored (L2 -> GEMM via ||q-k||^2 expansion).
__global__ __launch_bounds__(256) void proj_kernel(
    const float* __restrict__ x,
    const float* __restrict__ Wq, const float* __restrict__ bq,
    const float* __restrict__ Wk, const float* __restrict__ bk,
    const float* __restrict__ Wv, const float* __restrict__ bv)
{
    const int ct = blockIdx.x;            // 0..11 -> (s,h)
    const int rt = blockIdx.y;            // 0..7 row tile
    const int b  = blockIdx.z;
    const int s = ct >> 2, h = ct & 3;

    const float* W   = (s == 0 ? Wq : (s == 1 ? Wk : Wv)) + h * DD * EE;
    const float* bia = (s == 0 ? bq : (s == 1 ? bk : bv)) + h * EE;
    float* out = (s == 0 ? g_q : (s == 1 ? g_k : g_v)) + (size_t)(h * BB + b) * NN * EE;
    const float* X = x + (size_t)(b * NN + rt * 64) * DD;

    __shared__ float As[32][64];   // [kk][row]  (transposed)
    __shared__ float Bs[32][64];   // [kk][col]

    const int tid = threadIdx.x;
    const int tx = tid & 15, ty = tid >> 4;

    float acc[4][4] = {};

    for (int kc = 0; kc < DD; kc += 32) {
        #pragma unroll
        for (int t = 0; t < 2; t++) {
            int lin = tid + t * 256;                  // 0..511 float4 units
            int r = lin >> 3, c = (lin & 7) * 4;      // A: row r, k-offset c
            float4 va = *(const float4*)&X[r * DD + kc + c];
            As[c + 0][r] = va.x; As[c + 1][r] = va.y;
            As[c + 2][r] = va.z; As[c + 3][r] = va.w;
            int kk = lin >> 4, cc = (lin & 15) * 4;   // B: k row kk, col cc
            float4 vb = *(const float4*)&W[(kc + kk) * EE + cc];
            *(float4*)&Bs[kk][cc] = vb;
        }
        __syncthreads();
        #pragma unroll
        for (int kk = 0; kk < 32; kk++) {
            float4 a  = *(const float4*)&As[kk][ty * 4];
            float4 bb = *(const float4*)&Bs[kk][tx * 4];
            float av[4] = {a.x, a.y, a.z, a.w};
            float bw[4] = {bb.x, bb.y, bb.z, bb.w};
            #pragma unroll
            for (int i = 0; i < 4; i++)
                #pragma unroll
                for (int j = 0; j < 4; j++)
                    acc[i][j] = fmaf(av[i], bw[j], acc[i][j]);
        }
        __syncthreads();
    }

    const bool norm_head = (s < 2) && (h == 1 || h == 3);

    #pragma unroll
    for (int i = 0; i < 4; i++) {
        float4 o;
        o.x = acc[i][0] + bia[tx * 4 + 0];
        o.y = acc[i][1] + bia[tx * 4 + 1];
        o.z = acc[i][2] + bia[tx * 4 + 2];
        o.w = acc[i][3] + bia[tx * 4 + 3];
        if (norm_head) {
            // row sum-of-squares across the 16 tx lanes (same half-warp)
            float ss = o.x*o.x + o.y*o.y + o.z*o.z + o.w*o.w;
            #pragma unroll
            for (int off = 8; off; off >>= 1)
                ss += __shfl_xor_sync(0xffffffffu, ss, off);
            if (h == 1) {               // cosine: normalize rows in place
                float sc = rsqrtf(ss);
                o.x *= sc; o.y *= sc; o.z *= sc; o.w *= sc;
            } else if (tx == 0) {       // L2: stash sq-norm
                float* dst = (s == 0 ? g_qn : g_kn);
                dst[b * NN + rt * 64 + ty * 4 + i] = ss;
            }
        }
        *(float4*)&out[(size_t)(rt * 64 + ty * 4 + i) * EE + tx * 4] = o;
    }
}

// ---------------- 2a) unified dot-product logits (heads 0,1,3) ----------------
// blockIdx.z = m*BB + b, m: 0->sdp(h0), 1->cosine(h1, pre-normalized), 2->L2(h3).
// e-chunked tiles (stride 36; 36 mod 32 = 4 -> conflict-free LDS.128).
__global__ __launch_bounds__(256) void logits_gemm_kernel()
{
    const int jt = blockIdx.x, it = blockIdx.y;
    const int m = blockIdx.z / BB, b = blockIdx.z % BB;
    const int h = (m == 2) ? 3 : m;
    const float* Q = g_q + ((size_t)(h * BB + b) * NN + it * 64) * EE;
    const float* K = g_k + ((size_t)(h * BB + b) * NN + jt * 64) * EE;
    float* L = g_logits + ((size_t)(h * BB + b) * NN + it * 64) * NN + jt * 64;

    __shared__ float Qs[64][36];
    __shared__ float Ks[64][36];
    __shared__ float qn[64], kn[64];

    const int tid = threadIdx.x;
    const int tx = tid & 15, ty = tid >> 4;

    if (m == 2) {
        if (tid < 64)       qn[tid]      = g_qn[b * NN + it * 64 + tid];
        else if (tid < 128) kn[tid - 64] = g_kn[b * NN + jt * 64 + (tid - 64)];
    }

    float acc[4][4] = {};
    for (int kc = 0; kc < EE; kc += 32) {
        __syncthreads();
        #pragma unroll
        for (int t = 0; t < 2; t++) {
            int lin = tid + t * 256;               // 0..511 float4 units
            int r = lin >> 3, c = (lin & 7) * 4;
            *(float4*)&Qs[r][c] = *(const float4*)&Q[r * EE + kc + c];
            *(float4*)&Ks[r][c] = *(const float4*)&K[r * EE + kc + c];
        }
        __syncthreads();
        #pragma unroll
        for (int e = 0; e < 32; e += 4) {
            float4 q4[4], k4[4];
            #pragma unroll
            for (int ii = 0; ii < 4; ii++) q4[ii] = *(const float4*)&Qs[ty * 4 + ii][e];
            #pragma unroll
            for (int jj = 0; jj < 4; jj++) k4[jj] = *(const float4*)&Ks[tx + 16 * jj][e];
            #pragma unroll
            for (int ii = 0; ii < 4; ii++)
                #pragma unroll
                for (int jj = 0; jj < 4; jj++) {
                    acc[ii][jj] = fmaf(q4[ii].x, k4[jj].x, acc[ii][jj]);
                    acc[ii][jj] = fmaf(q4[ii].y, k4[jj].y, acc[ii][jj]);
                    acc[ii][jj] = fmaf(q4[ii].z, k4[jj].z, acc[ii][jj]);
                    acc[ii][jj] = fmaf(q4[ii].w, k4[jj].w, acc[ii][jj]);
                }
        }
    }

    #pragma unroll
    for (int ii = 0; ii < 4; ii++) {
        #pragma unroll
        for (int jj = 0; jj < 4; jj++) {
            float v = acc[ii][jj];
            if (m == 0)      v *= 0.125f;                                 // 1/sqrt(E)
            else if (m == 2) v = -sqrtf(fmaxf(qn[ty * 4 + ii] + kn[tx + 16 * jj] - 2.0f * v, 0.0f));
            L[(size_t)(ty * 4 + ii) * NN + tx + 16 * jj] = v;
        }
    }
}

// ---------------- 2b) L1 logits (head 2, elementwise |q-k|) ----------------
__global__ __launch_bounds__(256) void logits_l1_kernel()
{
    const int jt = blockIdx.x, it = blockIdx.y, b = blockIdx.z;
    const float* Q = g_q + ((size_t)(2 * BB + b) * NN + it * 64) * EE;
    const float* K = g_k + ((size_t)(2 * BB + b) * NN + jt * 64) * EE;
    float* L = g_logits + ((size_t)(2 * BB + b) * NN + it * 64) * NN + jt * 64;

    __shared__ float Qs[64][36];
    __shared__ float Ks[64][36];

    const int tid = threadIdx.x;
    const int tx = tid & 15, ty = tid >> 4;

    float acc[4][4] = {};
    for (int kc = 0; kc < EE; kc += 32) {
        __syncthreads();
        #pragma unroll
        for (int t = 0; t < 2; t++) {
            int lin = tid + t * 256;
            int r = lin >> 3, c = (lin & 7) * 4;
            *(float4*)&Qs[r][c] = *(const float4*)&Q[r * EE + kc + c];
            *(float4*)&Ks[r][c] = *(const float4*)&K[r * EE + kc + c];
        }
        __syncthreads();
        #pragma unroll
        for (int e = 0; e < 32; e += 4) {
            float4 q4[4], k4[4];
            #pragma unroll
            for (int ii = 0; ii < 4; ii++) q4[ii] = *(const float4*)&Qs[ty * 4 + ii][e];
            #pragma unroll
            for (int jj = 0; jj < 4; jj++) k4[jj] = *(const float4*)&Ks[tx + 16 * jj][e];
            #pragma unroll
            for (int ii = 0; ii < 4; ii++)
                #pragma unroll
                for (int jj = 0; jj < 4; jj++) {
                    acc[ii][jj] += fabsf(q4[ii].x - k4[jj].x);
                    acc[ii][jj] += fabsf(q4[ii].y - k4[jj].y);
                    acc[ii][jj] += fabsf(q4[ii].z - k4[jj].z);
                    acc[ii][jj] += fabsf(q4[ii].w - k4[jj].w);
                }
        }
    }

    #pragma unroll
    for (int ii = 0; ii < 4; ii++)
        #pragma unroll
        for (int jj = 0; jj < 4; jj++)
            L[(size_t)(ty * 4 + ii) * NN + tx + 16 * jj] = -acc[ii][jj];
}

// ---------------- 3) fused softmax + P @ V + head concat ----------------
__global__ __launch_bounds__(256) void av_kernel(float* __restrict__ out)
{
    const int it = blockIdx.x, h = blockIdx.y, b = blockIdx.z;
    const float* P = g_logits + ((size_t)(h * BB + b) * NN + it * 16) * NN;
    const float* V = g_v + (size_t)(h * BB + b) * NN * EE;
    float* O = out + ((size_t)(b * NN + it * 16)) * (HH * EE) + h * EE;

    __shared__ float Ls[16][516];
    __shared__ float Vs[32][64];
    __shared__ float invs[16];

    const int tid = threadIdx.x;

    for (int i = tid; i < 16 * 128; i += 256) {
        int r = i >> 7, c = (i & 127) * 4;
        *(float4*)&Ls[r][c] = *(const float4*)&P[(size_t)r * NN + c];
    }
    __syncthreads();

    {
        const int warp = tid >> 5, lane = tid & 31;
        #pragma unroll
        for (int rr = 0; rr < 2; rr++) {
            const int r = warp * 2 + rr;
            float vals[16];
            float mx = -1e30f;
            #pragma unroll
            for (int t = 0; t < 16; t++) { vals[t] = Ls[r][lane + t * 32]; mx = fmaxf(mx, vals[t]); }
            #pragma unroll
            for (int o = 16; o; o >>= 1) mx = fmaxf(mx, __shfl_xor_sync(0xffffffffu, mx, o));
            float sum = 0.f;
            #pragma unroll
            for (int t = 0; t < 16; t++) {
                vals[t] = __expf(vals[t] - mx);
                Ls[r][lane + t * 32] = vals[t];
                sum += vals[t];
            }
            #pragma unroll
            for (int o = 16; o; o >>= 1) sum += __shfl_xor_sync(0xffffffffu, sum, o);
            if (lane == 0) invs[r] = 1.0f / sum;
        }
    }
    __syncthreads();

    const int tx = tid & 15, ty = tid >> 4;
    float ax = 0.f, ay = 0.f, az = 0.f, aw = 0.f;
    for (int kc = 0; kc < NN; kc += 32) {
        #pragma unroll
        for (int t = 0; t < 2; t++) {
            int lin = tid + t * 256;
            int kk = lin >> 4, c = (lin & 15) * 4;
            *(float4*)&Vs[kk][c] = *(const float4*)&V[(size_t)(kc + kk) * EE + c];
        }
        __syncthreads();
        #pragma unroll
        for (int kk = 0; kk < 32; kk += 4) {
            float4 p = *(const float4*)&Ls[ty][kc + kk];
            float4 v0 = *(const float4*)&Vs[kk + 0][tx * 4];
            float4 v1 = *(const float4*)&Vs[kk + 1][tx * 4];
            float4 v2 = *(const float4*)&Vs[kk + 2][tx * 4];
            float4 v3 = *(const float4*)&Vs[kk + 3][tx * 4];
            ax = fmaf(p.x, v0.x, ax); ay = fmaf(p.x, v0.y, ay);
            az = fmaf(p.x, v0.z, az); aw = fmaf(p.x, v0.w, aw);
            ax = fmaf(p.y, v1.x, ax); ay = fmaf(p.y, v1.y, ay);
            az = fmaf(p.y, v1.z, az); aw = fmaf(p.y, v1.w, aw);
            ax = fmaf(p.z, v2.x, ax); ay = fmaf(p.z, v2.y, ay);
            az = fmaf(p.z, v2.z, az); aw = fmaf(p.z, v2.w, aw);
            ax = fmaf(p.w, v3.x, ax); ay = fmaf(p.w, v3.y, ay);
            az = fmaf(p.w, v3.z, az); aw = fmaf(p.w, v3.w, aw);
        }
        __syncthreads();
    }
    const float inv = invs[ty];
    float4 o = { ax * inv, ay * inv, az * inv, aw * inv };
    *(float4*)&O[(size_t)ty * (HH * EE) + tx * 4] = o;
}

// ---------------- launch ----------------
extern "C" void kernel_launch(void* const* d_in, const int* in_sizes, int n_in,
                              void* d_out, int out_size)
{
    (void)in_sizes; (void)n_in; (void)out_size;
    const float* x  = (const float*)d_in[0];
    const float* Wq = (const float*)d_in[1];
    const float* bq = (const float*)d_in[2];
    const float* Wk = (const float*)d_in[3];
    const float* bk = (const float*)d_in[4];
    const float* Wv = (const float*)d_in[5];
    const float* bv = (const float*)d_in[6];
    float* out = (float*)d_out;

    proj_kernel<<<dim3(12, 8, BB), 256>>>(x, Wq, bq, Wk, bk, Wv, bv);
    logits_gemm_kernel<<<dim3(8, 8, 3 * BB), 256>>>();
    logits_l1_kernel<<<dim3(8, 8, BB), 256>>>();
    av_kernel<<<dim3(32, HH, BB), 256>>>(out);
}